// round 2
// baseline (speedup 1.0000x reference)
#include <cuda_runtime.h>
#include <cuda_bf16.h>

// ImagemoveCollisionCost: per-point bilinear SDF + gradient sampling, cost fusion.
//   state_seq : [B=8192, T=128, 4] f32  (x, y, vx, vy)
//   sdf       : [2048, 2048] f32
//   grad_y    : [2048, 2048] f32
//   grad_x    : [2048, 2048] f32
// Outputs (concatenated): res [B*T], judge_res [B*T]  -> d_out has 2*N floats.

#define W_IMG  2048
#define H_IMG  2048
#define LO    (-1.0f)
#define HI    ( 1.0f)
#define WV1   (1.0f)   // vec_weight[0]
#define WV2   (0.5f)   // vec_weight[1]

__global__ __launch_bounds__(256, 8)
void imgmove_cost_kernel(const float4* __restrict__ state,   // N points
                         const float*  __restrict__ sdf,
                         const float*  __restrict__ gym,
                         const float*  __restrict__ gxm,
                         float*        __restrict__ out_res,
                         float*        __restrict__ out_judge,
                         int n)
{
    int i = blockIdx.x * blockDim.x + threadIdx.x;
    if (i >= n) return;

    float4 s = state[i];               // coalesced 16B
    float x = s.x, y = s.y, vx = s.z, vy = s.w;

    // world -> pixel, clipped in-bounds
    const float sc = 0.5f * (float)(W_IMG - 1);   // (HI-LO)=2
    float px = fminf(fmaxf((x - LO) * sc, 0.0f), (float)(W_IMG - 1));
    float py = fminf(fmaxf((y - LO) * sc, 0.0f), (float)(H_IMG - 1));

    int x0 = (int)floorf(px);
    int y0 = (int)floorf(py);
    x0 = min(max(x0, 0), W_IMG - 2);
    y0 = min(max(y0, 0), H_IMG - 2);
    float fx = px - (float)x0;
    float fy = py - (float)y0;

    int idx00 = y0 * W_IMG + x0;       // shared by all three maps
    int idx10 = idx00 + W_IMG;

    // Issue all 12 gathers back-to-back for max MLP (long-scoreboard hiding).
    float s00 = __ldg(sdf + idx00);
    float s01 = __ldg(sdf + idx00 + 1);
    float s10 = __ldg(sdf + idx10);
    float s11 = __ldg(sdf + idx10 + 1);
    float a00 = __ldg(gym + idx00);
    float a01 = __ldg(gym + idx00 + 1);
    float a10 = __ldg(gym + idx10);
    float a11 = __ldg(gym + idx10 + 1);
    float b00 = __ldg(gxm + idx00);
    float b01 = __ldg(gxm + idx00 + 1);
    float b10 = __ldg(gxm + idx10);
    float b11 = __ldg(gxm + idx10 + 1);

    // bilinear weights
    float gx1 = 1.0f - fx;
    float gy1 = 1.0f - fy;

    float pot = (s00 * gx1 + s01 * fx) * gy1 + (s10 * gx1 + s11 * fx) * fy;
    float gy_ = (a00 * gx1 + a01 * fx) * gy1 + (a10 * gx1 + a11 * fx) * fy;
    float gx_ = (b00 * gx1 + b01 * fx) * gy1 + (b10 * gx1 + b11 * fx) * fy;

    float vel_abs  = sqrtf(vx * vx + vy * vy);
    float grad_abs = sqrtf(gx_ * gx_ + gy_ * gy_);
    float dot      = vx * gx_ + vy * gy_;
    float cosq     = dot / (vel_abs * grad_abs + 1e-6f);
    cosq = fminf(fmaxf(cosq, -1.0f), 1.0f);
    float neg_cos = -cosq;

    float pv     = WV2 * pot * vel_abs;
    float judge  = WV1 * pot + pv;
    float factor = 1.0f + fmaxf(neg_cos, 0.0f) + 0.8f * fminf(neg_cos, 0.0f);
    float cost   = WV1 * pot + pv * factor;

    out_res[i]   = cost;    // WEIGHT = 1.0
    out_judge[i] = judge;
}

extern "C" void kernel_launch(void* const* d_in, const int* in_sizes, int n_in,
                              void* d_out, int out_size)
{
    const float4* state = (const float4*)d_in[0];
    const float*  sdf   = (const float*)d_in[1];
    const float*  gym   = (const float*)d_in[2];
    const float*  gxm   = (const float*)d_in[3];
    float* out = (float*)d_out;

    int n = in_sizes[0] / 4;           // B*T points
    float* out_res   = out;
    float* out_judge = out + n;

    int threads = 256;
    int blocks  = (n + threads - 1) / threads;
    imgmove_cost_kernel<<<blocks, threads>>>(state, sdf, gym, gxm,
                                             out_res, out_judge, n);
}

// round 3
// speedup vs baseline: 1.3170x; 1.3170x over previous
#include <cuda_runtime.h>
#include <cuda_bf16.h>

// ImagemoveCollisionCost: per-point bilinear SDF + gradient sampling, cost fusion.
//   state_seq : [8192, 128, 4] f32  (x, y, vx, vy)
//   sdf, grad_y, grad_x : [2048, 2048] f32
// Outputs concatenated: res [N], judge_res [N]  (N = 1048576).
//
// R2: merge each row's x-corner pair (x0, x0+1) into one aligned LDG.128 at
// x0 & ~3; predicated scalar load covers the off==3 wrap case. Cuts scattered
// L1 wavefronts from 12/pt to ~7.5/pt (L1tex was the 78% bottleneck).

#define W_IMG  2048
#define H_IMG  2048
#define LO    (-1.0f)
#define WV1   (1.0f)
#define WV2   (0.5f)

// Extract window[off] and window[off+1] from an aligned float4 (+ extra for off==3).
__device__ __forceinline__ void pick2(float4 q, float e, int off,
                                      float& v0, float& v1)
{
    bool hi = (off & 2) != 0;
    bool lo = (off & 1) != 0;
    v0 = hi ? (lo ? q.w : q.z) : (lo ? q.y : q.x);
    v1 = hi ? (lo ? e   : q.w) : (lo ? q.z : q.y);
}

__global__ __launch_bounds__(256, 4)
void imgmove_cost_kernel(const float4* __restrict__ state,
                         const float*  __restrict__ sdf,
                         const float*  __restrict__ gym,
                         const float*  __restrict__ gxm,
                         float*        __restrict__ out_res,
                         float*        __restrict__ out_judge,
                         int n)
{
    int i = blockIdx.x * blockDim.x + threadIdx.x;
    if (i >= n) return;

    float4 s = state[i];
    float x = s.x, y = s.y, vx = s.z, vy = s.w;

    const float sc = 0.5f * (float)(W_IMG - 1);
    float px = fminf(fmaxf((x - LO) * sc, 0.0f), (float)(W_IMG - 1));
    float py = fminf(fmaxf((y - LO) * sc, 0.0f), (float)(H_IMG - 1));

    int x0 = (int)floorf(px);
    int y0 = (int)floorf(py);
    x0 = min(max(x0, 0), W_IMG - 2);
    y0 = min(max(y0, 0), H_IMG - 2);
    float fx = px - (float)x0;
    float fy = py - (float)y0;

    int x0a = x0 & ~3;          // 16B-aligned window start
    int off = x0 - x0a;         // 0..3
    int b0  = y0 * W_IMG + x0a; // row y0 window
    int b1  = b0 + W_IMG;       // row y0+1 window
    bool wrap = (off == 3);

    // 6 vector gathers + up to 6 predicated scalar gathers, all issued
    // back-to-back for max MLP.
    float4 S0 = __ldg((const float4*)(sdf + b0));
    float4 S1 = __ldg((const float4*)(sdf + b1));
    float4 A0 = __ldg((const float4*)(gym + b0));
    float4 A1 = __ldg((const float4*)(gym + b1));
    float4 B0 = __ldg((const float4*)(gxm + b0));
    float4 B1 = __ldg((const float4*)(gxm + b1));
    float se0 = wrap ? __ldg(sdf + b0 + 4) : 0.0f;
    float se1 = wrap ? __ldg(sdf + b1 + 4) : 0.0f;
    float ae0 = wrap ? __ldg(gym + b0 + 4) : 0.0f;
    float ae1 = wrap ? __ldg(gym + b1 + 4) : 0.0f;
    float be0 = wrap ? __ldg(gxm + b0 + 4) : 0.0f;
    float be1 = wrap ? __ldg(gxm + b1 + 4) : 0.0f;

    float s00, s01, s10, s11;
    float a00, a01, a10, a11;
    float c00, c01, c10, c11;
    pick2(S0, se0, off, s00, s01);
    pick2(S1, se1, off, s10, s11);
    pick2(A0, ae0, off, a00, a01);
    pick2(A1, ae1, off, a10, a11);
    pick2(B0, be0, off, c00, c01);
    pick2(B1, be1, off, c10, c11);

    float gx1 = 1.0f - fx;
    float gy1 = 1.0f - fy;

    float pot = (s00 * gx1 + s01 * fx) * gy1 + (s10 * gx1 + s11 * fx) * fy;
    float gy_ = (a00 * gx1 + a01 * fx) * gy1 + (a10 * gx1 + a11 * fx) * fy;
    float gx_ = (c00 * gx1 + c01 * fx) * gy1 + (c10 * gx1 + c11 * fx) * fy;

    float vel_abs  = sqrtf(vx * vx + vy * vy);
    float grad_abs = sqrtf(gx_ * gx_ + gy_ * gy_);
    float dot      = vx * gx_ + vy * gy_;
    float cosq     = dot / (vel_abs * grad_abs + 1e-6f);
    cosq = fminf(fmaxf(cosq, -1.0f), 1.0f);
    float neg_cos = -cosq;

    float pv     = WV2 * pot * vel_abs;
    float judge  = WV1 * pot + pv;
    float factor = 1.0f + fmaxf(neg_cos, 0.0f) + 0.8f * fminf(neg_cos, 0.0f);
    float cost   = WV1 * pot + pv * factor;

    out_res[i]   = cost;
    out_judge[i] = judge;
}

extern "C" void kernel_launch(void* const* d_in, const int* in_sizes, int n_in,
                              void* d_out, int out_size)
{
    const float4* state = (const float4*)d_in[0];
    const float*  sdf   = (const float*)d_in[1];
    const float*  gym   = (const float*)d_in[2];
    const float*  gxm   = (const float*)d_in[3];
    float* out = (float*)d_out;

    int n = in_sizes[0] / 4;
    float* out_res   = out;
    float* out_judge = out + n;

    int threads = 256;
    int blocks  = (n + threads - 1) / threads;
    imgmove_cost_kernel<<<blocks, threads>>>(state, sdf, gym, gxm,
                                             out_res, out_judge, n);
}